// round 5
// baseline (speedup 1.0000x reference)
#include <cuda_runtime.h>
#include <cuda_bf16.h>
#include <math_constants.h>

#define N_FEAT 500000
#define DIM    768
#define NQ     64
#define TOPK   5
#define SEGLEN 512
#define TILE   128
#define KC     32
#define NBLK   ((N_FEAT + TILE - 1) / TILE)   // 3907

// Candidate scratch: per (block, query) top-5. 3907*64*5 = 1,250,240 entries.
__device__ float g_cand_v[(size_t)NBLK * NQ * TOPK];
__device__ int   g_cand_i[(size_t)NBLK * NQ * TOPK];
__device__ int   g_top[NQ * TOPK];

__device__ __forceinline__ bool better(float av, int ai, float bv, int bi) {
    return (av > bv) || (av == bv && ai < bi);
}

// ---------------------------------------------------------------------------
// Stage 1 (fused): tile GEMM (128 features x 64 queries) -> scale by
// rsqrt(|f|^2) (query norm omitted: per-query positive constant,
// rank-invariant) -> per-warp top-5 per query -> candidate buffer.
// ---------------------------------------------------------------------------
__global__ __launch_bounds__(256)
void score_topk_kernel(const float* __restrict__ qf, const float* __restrict__ ff) {
    __shared__ float sf[KC][132];
    __shared__ float sq[KC][68];
    __shared__ float sscale[TILE];

    const int tid = threadIdx.x;
    const int qg  = tid >> 5;       // warp id: handles queries 8*qg..8*qg+7
    const int fg  = tid & 31;       // lane: feature rows n0 + 4*fg .. +3
    const long n0 = (long)blockIdx.x * TILE;

    float acc[4][8];
    #pragma unroll
    for (int r = 0; r < 4; r++)
        #pragma unroll
        for (int c = 0; c < 8; c++) acc[r][c] = 0.0f;
    float nrm[4] = {0.f, 0.f, 0.f, 0.f};

    for (int d0 = 0; d0 < DIM; d0 += KC) {
        #pragma unroll
        for (int i = 0; i < 4; i++) {
            int id  = tid + 256 * i;      // 0..1023
            int row = id >> 3;            // 0..127
            int c4  = id & 7;             // 0..7
            long n  = n0 + row;
            float4 v = make_float4(0.f, 0.f, 0.f, 0.f);
            if (n < N_FEAT)
                v = *(const float4*)&ff[n * (long)DIM + d0 + 4 * c4];
            sf[4 * c4 + 0][row] = v.x;
            sf[4 * c4 + 1][row] = v.y;
            sf[4 * c4 + 2][row] = v.z;
            sf[4 * c4 + 3][row] = v.w;
        }
        #pragma unroll
        for (int i = 0; i < 2; i++) {
            int id  = tid + 256 * i;      // 0..511
            int row = id >> 3;            // 0..63
            int c4  = id & 7;
            float4 v = *(const float4*)&qf[row * DIM + d0 + 4 * c4];
            sq[4 * c4 + 0][row] = v.x;
            sq[4 * c4 + 1][row] = v.y;
            sq[4 * c4 + 2][row] = v.z;
            sq[4 * c4 + 3][row] = v.w;
        }
        __syncthreads();

        #pragma unroll
        for (int d = 0; d < KC; d++) {
            float4 a  = *(const float4*)&sf[d][4 * fg];
            float4 b0 = *(const float4*)&sq[d][8 * qg];
            float4 b1 = *(const float4*)&sq[d][8 * qg + 4];
            float av[4] = {a.x, a.y, a.z, a.w};
            float bv[8] = {b0.x, b0.y, b0.z, b0.w, b1.x, b1.y, b1.z, b1.w};
            #pragma unroll
            for (int r = 0; r < 4; r++)
                #pragma unroll
                for (int c = 0; c < 8; c++)
                    acc[r][c] = fmaf(av[r], bv[c], acc[r][c]);
            if (qg == 0) {
                #pragma unroll
                for (int r = 0; r < 4; r++) nrm[r] = fmaf(av[r], av[r], nrm[r]);
            }
        }
        __syncthreads();
    }

    if (qg == 0) {
        #pragma unroll
        for (int r = 0; r < 4; r++)
            sscale[4 * fg + r] = (nrm[r] > 0.f) ? rsqrtf(nrm[r]) : 0.f;
    }
    __syncthreads();

    float s[4];
    int   fidx[4];
    bool  valid[4];
    #pragma unroll
    for (int r = 0; r < 4; r++) {
        long n = n0 + 4 * fg + r;
        s[r]     = sscale[4 * fg + r];
        valid[r] = (n < N_FEAT);
        fidx[r]  = valid[r] ? (int)n : (0x7ff00000 + 4 * fg + r);  // unique pad ids
    }

    // Per query c: warp top-5 over 128 values (4 per lane), 5 argmax rounds.
    #pragma unroll 1
    for (int c = 0; c < 8; c++) {
        float v[4];
        #pragma unroll
        for (int r = 0; r < 4; r++)
            v[r] = valid[r] ? acc[r][c] * s[r] : -CUDART_INF_F;
        bool used[4] = {false, false, false, false};

        const int q = 8 * qg + c;
        #pragma unroll 1
        for (int sel = 0; sel < TOPK; sel++) {
            float bv = -CUDART_INF_F; int bi = 0x7fffffff;
            #pragma unroll
            for (int r = 0; r < 4; r++)
                if (!used[r] && better(v[r], fidx[r], bv, bi)) { bv = v[r]; bi = fidx[r]; }
            #pragma unroll
            for (int off = 16; off >= 1; off >>= 1) {
                float ov = __shfl_down_sync(0xffffffffu, bv, off);
                int   oi = __shfl_down_sync(0xffffffffu, bi, off);
                if (better(ov, oi, bv, bi)) { bv = ov; bi = oi; }
            }
            bv = __shfl_sync(0xffffffffu, bv, 0);
            bi = __shfl_sync(0xffffffffu, bi, 0);
            if (fg == 0) {
                size_t o = ((size_t)blockIdx.x * NQ + q) * TOPK + sel;
                g_cand_v[o] = bv;
                g_cand_i[o] = bi;
            }
            #pragma unroll
            for (int r = 0; r < 4; r++)
                if (fidx[r] == bi) used[r] = true;
        }
    }
}

// ---------------------------------------------------------------------------
// Stage 2: per query, reduce NBLK*5 = 19535 candidates -> final top-5.
// ---------------------------------------------------------------------------
__device__ __forceinline__ void insert5(float v, int idx, float tv[5], int ti[5]) {
    if (better(v, idx, tv[4], ti[4])) {
        tv[4] = v; ti[4] = idx;
        #pragma unroll
        for (int s = 4; s > 0; s--) {
            if (better(tv[s], ti[s], tv[s - 1], ti[s - 1])) {
                float fv = tv[s]; tv[s] = tv[s - 1]; tv[s - 1] = fv;
                int   fi = ti[s]; ti[s] = ti[s - 1]; ti[s - 1] = fi;
            }
        }
    }
}

__global__ __launch_bounds__(256)
void topk_final_kernel() {
    const int q   = blockIdx.x;
    const int tid = threadIdx.x;
    const int NC  = NBLK * TOPK;   // 19535

    float tv[TOPK]; int ti[TOPK];
    #pragma unroll
    for (int s = 0; s < TOPK; s++) { tv[s] = -CUDART_INF_F; ti[s] = 0x7fffffff; }

    for (int e = tid; e < NC; e += 256) {
        int blk = e / TOPK, sel = e % TOPK;
        size_t o = ((size_t)blk * NQ + q) * TOPK + sel;
        insert5(g_cand_v[o], g_cand_i[o], tv, ti);
    }

    __shared__ float sv[256 * TOPK];
    __shared__ int   si[256 * TOPK];
    #pragma unroll
    for (int s = 0; s < TOPK; s++) { sv[tid * TOPK + s] = tv[s]; si[tid * TOPK + s] = ti[s]; }
    __syncthreads();

    for (int off = 128; off >= 1; off >>= 1) {
        if (tid < off) {
            float ov[TOPK]; int oi[TOPK];
            #pragma unroll
            for (int s = 0; s < TOPK; s++) {
                ov[s] = sv[(tid + off) * TOPK + s];
                oi[s] = si[(tid + off) * TOPK + s];
            }
            float mv[TOPK]; int mi[TOPK];
            int i = 0, j = 0;
            #pragma unroll
            for (int o = 0; o < TOPK; o++) {
                if (better(tv[i], ti[i], ov[j], oi[j])) { mv[o] = tv[i]; mi[o] = ti[i]; i++; }
                else                                    { mv[o] = ov[j]; mi[o] = oi[j]; j++; }
            }
            #pragma unroll
            for (int s = 0; s < TOPK; s++) {
                tv[s] = mv[s]; ti[s] = mi[s];
                sv[tid * TOPK + s] = mv[s];
                si[tid * TOPK + s] = mi[s];
            }
        }
        __syncthreads();
    }

    // FIX (round 4): only thread 0 holds the fully merged top-5 after the
    // tree reduction. Writing ti[tid] from threads 1..4 published their
    // stale subtree partials (exactly the observed top-1-right/rest-wrong
    // signature, rel_err 0.61).
    if (tid == 0) {
        #pragma unroll
        for (int s = 0; s < TOPK; s++)
            g_top[q * TOPK + s] = ti[s];
    }
}

// ---------------------------------------------------------------------------
// Stage 3: gather data[idx][0:512] -> out[q][j][0:512], converted to fp32
// (output dtype is float32; vocab ints < 30522 are exactly representable).
// ---------------------------------------------------------------------------
__global__ __launch_bounds__(128)
void gather_kernel(const int* __restrict__ data, float* __restrict__ out) {
    const int r = blockIdx.x;
    int idx = g_top[r];
    idx = (idx < 0) ? 0 : ((idx >= N_FEAT) ? N_FEAT - 1 : idx);
    const int4* src = (const int4*)&data[(size_t)idx * SEGLEN];
    float4* dst = (float4*)&out[(size_t)r * SEGLEN];
    for (int t = threadIdx.x; t < SEGLEN / 4; t += blockDim.x) {
        int4 v = src[t];
        dst[t] = make_float4((float)v.x, (float)v.y, (float)v.z, (float)v.w);
    }
}

// ---------------------------------------------------------------------------
// Bind inputs by SIZE RANK (robust to element-vs-byte counts and ordering):
//   feature (largest) > data (2nd) > query_feature (3rd) > k (smallest)
// ---------------------------------------------------------------------------
extern "C" void kernel_launch(void* const* d_in, const int* in_sizes, int n_in,
                              void* d_out, int out_size) {
    (void)out_size;
    int i_ff = 0, i_dt = -1, i_qf = -1;
    for (int i = 1; i < n_in; i++)
        if ((unsigned)in_sizes[i] > (unsigned)in_sizes[i_ff]) i_ff = i;
    for (int i = 0; i < n_in; i++) {
        if (i == i_ff) continue;
        if (i_dt < 0 || (unsigned)in_sizes[i] > (unsigned)in_sizes[i_dt]) i_dt = i;
    }
    for (int i = 0; i < n_in; i++) {
        if (i == i_ff || i == i_dt) continue;
        if (i_qf < 0 || (unsigned)in_sizes[i] > (unsigned)in_sizes[i_qf]) i_qf = i;
    }
    const float* qf   = (const float*)d_in[i_qf >= 0 ? i_qf : 0];
    const float* ff   = (const float*)d_in[i_ff];
    const int*   data = (const int*)d_in[i_dt >= 0 ? i_dt : (n_in > 2 ? 2 : 0)];
    float* out = (float*)d_out;

    score_topk_kernel<<<NBLK, 256>>>(qf, ff);
    topk_final_kernel<<<NQ, 256>>>();
    gather_kernel<<<NQ * TOPK, 128>>>(data, out);
}

// round 6
// speedup vs baseline: 4.0483x; 4.0483x over previous
#include <cuda_runtime.h>
#include <cuda_bf16.h>
#include <math_constants.h>

#define N_FEAT 500000
#define DIM    768
#define NQ     64
#define TOPK   5
#define SEGLEN 512
#define TILE   128
#define KC     32
#define NBLK   ((N_FEAT + TILE - 1) / TILE)   // 3907

__device__ float g_cand_v[(size_t)NBLK * NQ * TOPK];
__device__ int   g_cand_i[(size_t)NBLK * NQ * TOPK];
__device__ int   g_top[NQ * TOPK];

__device__ __forceinline__ bool better(float av, int ai, float bv, int bi) {
    return (av > bv) || (av == bv && ai < bi);
}

// ---------------------------------------------------------------------------
// Stage 1 (fused): tile GEMM (128 features x 64 queries) -> scale by
// rsqrt(|f|^2) -> per-warp top-5 per query -> candidate buffer.
// R5 FIX: epilogue fully unrolled with compile-time indices so acc[4][8]
// stays in registers (the runtime-indexed `acc[r][c]` inside `#pragma
// unroll 1` loops demoted the whole accumulator to local memory => the
// L1=86%/L2=71%/fma=7.8% spill signature and the 9 ms runtime).
// ---------------------------------------------------------------------------
__global__ __launch_bounds__(256)
void score_topk_kernel(const float* __restrict__ qf, const float* __restrict__ ff) {
    __shared__ float sf[KC][132];
    __shared__ float sq[KC][68];
    __shared__ float sscale[TILE];

    const int tid = threadIdx.x;
    const int qg  = tid >> 5;       // warp id: queries 8*qg..8*qg+7
    const int fg  = tid & 31;       // lane: feature rows n0 + 4*fg .. +3
    const long n0 = (long)blockIdx.x * TILE;

    float acc[4][8];
    #pragma unroll
    for (int r = 0; r < 4; r++)
        #pragma unroll
        for (int c = 0; c < 8; c++) acc[r][c] = 0.0f;
    float nrm[4] = {0.f, 0.f, 0.f, 0.f};

    for (int d0 = 0; d0 < DIM; d0 += KC) {
        #pragma unroll
        for (int i = 0; i < 4; i++) {
            int id  = tid + 256 * i;      // 0..1023
            int row = id >> 3;            // 0..127
            int c4  = id & 7;             // 0..7
            long n  = n0 + row;
            float4 v = make_float4(0.f, 0.f, 0.f, 0.f);
            if (n < N_FEAT)
                v = *(const float4*)&ff[n * (long)DIM + d0 + 4 * c4];
            sf[4 * c4 + 0][row] = v.x;
            sf[4 * c4 + 1][row] = v.y;
            sf[4 * c4 + 2][row] = v.z;
            sf[4 * c4 + 3][row] = v.w;
        }
        #pragma unroll
        for (int i = 0; i < 2; i++) {
            int id  = tid + 256 * i;      // 0..511
            int row = id >> 3;            // 0..63
            int c4  = id & 7;
            float4 v = *(const float4*)&qf[row * DIM + d0 + 4 * c4];
            sq[4 * c4 + 0][row] = v.x;
            sq[4 * c4 + 1][row] = v.y;
            sq[4 * c4 + 2][row] = v.z;
            sq[4 * c4 + 3][row] = v.w;
        }
        __syncthreads();

        #pragma unroll
        for (int d = 0; d < KC; d++) {
            float4 a  = *(const float4*)&sf[d][4 * fg];
            float4 b0 = *(const float4*)&sq[d][8 * qg];
            float4 b1 = *(const float4*)&sq[d][8 * qg + 4];
            float av[4] = {a.x, a.y, a.z, a.w};
            float bv[8] = {b0.x, b0.y, b0.z, b0.w, b1.x, b1.y, b1.z, b1.w};
            #pragma unroll
            for (int r = 0; r < 4; r++)
                #pragma unroll
                for (int c = 0; c < 8; c++)
                    acc[r][c] = fmaf(av[r], bv[c], acc[r][c]);
            if (qg == 0) {
                #pragma unroll
                for (int r = 0; r < 4; r++) nrm[r] = fmaf(av[r], av[r], nrm[r]);
            }
        }
        __syncthreads();
    }

    if (qg == 0) {
        #pragma unroll
        for (int r = 0; r < 4; r++)
            sscale[4 * fg + r] = (nrm[r] > 0.f) ? rsqrtf(nrm[r]) : 0.f;
    }
    __syncthreads();

    float s[4];
    int   fidx[4];
    #pragma unroll
    for (int r = 0; r < 4; r++) {
        long n = n0 + 4 * fg + r;
        s[r]    = sscale[4 * fg + r];
        fidx[r] = (n < N_FEAT) ? (int)n : (0x7ff00000 + 4 * fg + r);  // unique pad ids
    }
    const bool tail = (n0 + TILE > N_FEAT);

    // Epilogue: per query (fully unrolled), warp top-5 via 5 argmax rounds
    // with shfl_xor butterfly (all lanes converge; no broadcast needed).
    #pragma unroll
    for (int c = 0; c < 8; c++) {
        float v[4];
        #pragma unroll
        for (int r = 0; r < 4; r++) {
            v[r] = acc[r][c] * s[r];
            if (tail && fidx[r] >= N_FEAT) v[r] = -CUDART_INF_F;
        }
        unsigned used = 0;
        const int q = 8 * qg + c;

        #pragma unroll
        for (int sel = 0; sel < TOPK; sel++) {
            float bv = -CUDART_INF_F; int bi = 0x7fffffff;
            #pragma unroll
            for (int r = 0; r < 4; r++)
                if (!(used & (1u << r)) && better(v[r], fidx[r], bv, bi)) {
                    bv = v[r]; bi = fidx[r];
                }
            #pragma unroll
            for (int off = 16; off >= 1; off >>= 1) {
                float ov = __shfl_xor_sync(0xffffffffu, bv, off);
                int   oi = __shfl_xor_sync(0xffffffffu, bi, off);
                if (better(ov, oi, bv, bi)) { bv = ov; bi = oi; }
            }
            if (fg == 0) {
                size_t o = ((size_t)blockIdx.x * NQ + q) * TOPK + sel;
                g_cand_v[o] = bv;
                g_cand_i[o] = bi;
            }
            #pragma unroll
            for (int r = 0; r < 4; r++)
                if (fidx[r] == bi) used |= (1u << r);
        }
    }
}

// ---------------------------------------------------------------------------
// Stage 2: per query, reduce NBLK*5 = 19535 candidates -> final top-5.
// ---------------------------------------------------------------------------
__device__ __forceinline__ void insert5(float v, int idx, float tv[5], int ti[5]) {
    if (better(v, idx, tv[4], ti[4])) {
        tv[4] = v; ti[4] = idx;
        #pragma unroll
        for (int s = 4; s > 0; s--) {
            if (better(tv[s], ti[s], tv[s - 1], ti[s - 1])) {
                float fv = tv[s]; tv[s] = tv[s - 1]; tv[s - 1] = fv;
                int   fi = ti[s]; ti[s] = ti[s - 1]; ti[s - 1] = fi;
            }
        }
    }
}

__global__ __launch_bounds__(256)
void topk_final_kernel() {
    const int q   = blockIdx.x;
    const int tid = threadIdx.x;
    const int NC  = NBLK * TOPK;   // 19535

    float tv[TOPK]; int ti[TOPK];
    #pragma unroll
    for (int s = 0; s < TOPK; s++) { tv[s] = -CUDART_INF_F; ti[s] = 0x7fffffff; }

    for (int e = tid; e < NC; e += 256) {
        int blk = e / TOPK, sel = e % TOPK;
        size_t o = ((size_t)blk * NQ + q) * TOPK + sel;
        insert5(g_cand_v[o], g_cand_i[o], tv, ti);
    }

    __shared__ float sv[256 * TOPK];
    __shared__ int   si[256 * TOPK];
    #pragma unroll
    for (int s = 0; s < TOPK; s++) { sv[tid * TOPK + s] = tv[s]; si[tid * TOPK + s] = ti[s]; }
    __syncthreads();

    for (int off = 128; off >= 1; off >>= 1) {
        if (tid < off) {
            float ov[TOPK]; int oi[TOPK];
            #pragma unroll
            for (int s = 0; s < TOPK; s++) {
                ov[s] = sv[(tid + off) * TOPK + s];
                oi[s] = si[(tid + off) * TOPK + s];
            }
            float mv[TOPK]; int mi[TOPK];
            int i = 0, j = 0;
            #pragma unroll
            for (int o = 0; o < TOPK; o++) {
                if (better(tv[i], ti[i], ov[j], oi[j])) { mv[o] = tv[i]; mi[o] = ti[i]; i++; }
                else                                    { mv[o] = ov[j]; mi[o] = oi[j]; j++; }
            }
            #pragma unroll
            for (int s = 0; s < TOPK; s++) {
                tv[s] = mv[s]; ti[s] = mi[s];
                sv[tid * TOPK + s] = mv[s];
                si[tid * TOPK + s] = mi[s];
            }
        }
        __syncthreads();
    }

    if (tid == 0) {   // only tid 0 holds the fully merged list (R4 fix)
        #pragma unroll
        for (int s = 0; s < TOPK; s++)
            g_top[q * TOPK + s] = ti[s];
    }
}

// ---------------------------------------------------------------------------
// Stage 3: gather + int->float convert (output dtype is float32).
// ---------------------------------------------------------------------------
__global__ __launch_bounds__(128)
void gather_kernel(const int* __restrict__ data, float* __restrict__ out) {
    const int r = blockIdx.x;
    int idx = g_top[r];
    idx = (idx < 0) ? 0 : ((idx >= N_FEAT) ? N_FEAT - 1 : idx);
    const int4* src = (const int4*)&data[(size_t)idx * SEGLEN];
    float4* dst = (float4*)&out[(size_t)r * SEGLEN];
    for (int t = threadIdx.x; t < SEGLEN / 4; t += blockDim.x) {
        int4 v = src[t];
        dst[t] = make_float4((float)v.x, (float)v.y, (float)v.z, (float)v.w);
    }
}

// ---------------------------------------------------------------------------
extern "C" void kernel_launch(void* const* d_in, const int* in_sizes, int n_in,
                              void* d_out, int out_size) {
    (void)out_size;
    int i_ff = 0, i_dt = -1, i_qf = -1;
    for (int i = 1; i < n_in; i++)
        if ((unsigned)in_sizes[i] > (unsigned)in_sizes[i_ff]) i_ff = i;
    for (int i = 0; i < n_in; i++) {
        if (i == i_ff) continue;
        if (i_dt < 0 || (unsigned)in_sizes[i] > (unsigned)in_sizes[i_dt]) i_dt = i;
    }
    for (int i = 0; i < n_in; i++) {
        if (i == i_ff || i == i_dt) continue;
        if (i_qf < 0 || (unsigned)in_sizes[i] > (unsigned)in_sizes[i_qf]) i_qf = i;
    }
    const float* qf   = (const float*)d_in[i_qf >= 0 ? i_qf : 0];
    const float* ff   = (const float*)d_in[i_ff];
    const int*   data = (const int*)d_in[i_dt >= 0 ? i_dt : (n_in > 2 ? 2 : 0)];
    float* out = (float*)d_out;

    score_topk_kernel<<<NBLK, 256>>>(qf, ff);
    topk_final_kernel<<<NQ, 256>>>();
    gather_kernel<<<NQ * TOPK, 128>>>(data, out);
}

// round 8
// speedup vs baseline: 8.3595x; 2.0650x over previous
#include <cuda_runtime.h>
#include <cuda_bf16.h>
#include <math_constants.h>
#include <cstdint>

#define N_FEAT 500000
#define DIM    768
#define NQ     64
#define TOPK   5
#define SEGLEN 512
#define M_TILE 128
#define KCH    64                          // k columns per chunk
#define NCHUNK (DIM / KCH)                 // 12
#define NBLK   ((N_FEAT + M_TILE - 1) / M_TILE)   // 3907
#define NCAND  8

#define SA_STRIDE 72    // bf16 elems per row (64 + 8 pad)
#define ST_STRIDE 136   // transpose buffer stride (128 + 8 pad)

// ---------------- scratch ----------------
__device__ __align__(16) __nv_bfloat16 g_qb[NQ * DIM];
__device__ __align__(16) __nv_bfloat16 g_scores[(size_t)NQ * N_FEAT];  // 64MB
__device__ int   g_cand[NQ * NCAND];
__device__ float g_exact[NQ * NCAND];
__device__ int   g_top[NQ * TOPK];

__device__ __forceinline__ bool better(float av, int ai, float bv, int bi) {
    return (av > bv) || (av == bv && ai < bi);
}

__device__ __forceinline__ void mma16816(float& c0, float& c1, float& c2, float& c3,
                                         uint32_t a0, uint32_t a1, uint32_t a2, uint32_t a3,
                                         uint32_t b0, uint32_t b1) {
    asm volatile(
        "mma.sync.aligned.m16n8k16.row.col.f32.bf16.bf16.f32 "
        "{%0,%1,%2,%3}, {%4,%5,%6,%7}, {%8,%9}, {%0,%1,%2,%3};"
        : "+f"(c0), "+f"(c1), "+f"(c2), "+f"(c3)
        : "r"(a0), "r"(a1), "r"(a2), "r"(a3), "r"(b0), "r"(b1));
}

// ---------------------------------------------------------------------------
// k0: queries fp32 -> bf16
// ---------------------------------------------------------------------------
__global__ void qconv_kernel(const float* __restrict__ qf) {
    int i = blockIdx.x * 256 + threadIdx.x;
    if (i < NQ * DIM / 2) {
        float2 f = ((const float2*)qf)[i];
        ((__nv_bfloat162*)g_qb)[i] = __float22bfloat162_rn(f);
    }
}

// ---------------------------------------------------------------------------
// k1: bf16 warp-MMA GEMM (128 feat x 64 q, K=768) + fp32 norms + scaled
//     bf16 score writeback (SMEM transpose for coalescing).
// mma.sync m16n8k16 (baseline PTX, valid on target sm_103 — tcgen05 is not).
// ---------------------------------------------------------------------------
__global__ __launch_bounds__(256)
void mma_score_kernel(const float* __restrict__ ff) {
    __shared__ __nv_bfloat16 sa[M_TILE * SA_STRIDE];   // 18432B, reused as transpose buf
    __shared__ __nv_bfloat16 sb[NQ * SA_STRIDE];       // 9216B
    __shared__ float snrm[M_TILE];

    const int tid = threadIdx.x;
    const int wid = tid >> 5;
    const int lid = tid & 31;
    const int g   = lid >> 2;      // mma group id (0..7)
    const int tg  = lid & 3;       // thread in group
    const long n0 = (long)blockIdx.x * M_TILE;

    if (tid < M_TILE) snrm[tid] = 0.f;

    float acc[8][4];
    #pragma unroll
    for (int nt = 0; nt < 8; nt++)
        #pragma unroll
        for (int r = 0; r < 4; r++) acc[nt][r] = 0.f;
    float npart[8] = {0.f, 0.f, 0.f, 0.f, 0.f, 0.f, 0.f, 0.f};
    // conversion slot i handles feature row (tid>>4) + 16*i

    for (int c = 0; c < NCHUNK; c++) {
        const int k0c = c * KCH;

        // --- A: 128 rows x 64 fp32 -> bf16 SMEM (+ norm partials) ---
        #pragma unroll
        for (int i = 0; i < 8; i++) {
            int id  = tid + 256 * i;        // 0..2047
            int row = id >> 4;              // == (tid>>4) + 16*i
            int j   = id & 15;              // float4 index within 64 cols
            long n  = n0 + row;
            float4 v = make_float4(0.f, 0.f, 0.f, 0.f);
            if (n < N_FEAT) v = *(const float4*)&ff[n * (long)DIM + k0c + 4 * j];
            npart[i] = fmaf(v.x, v.x, fmaf(v.y, v.y, fmaf(v.z, v.z, fmaf(v.w, v.w, npart[i]))));
            __nv_bfloat162 p0 = __float22bfloat162_rn(make_float2(v.x, v.y));
            __nv_bfloat162 p1 = __float22bfloat162_rn(make_float2(v.z, v.w));
            *(uint2*)&sa[row * SA_STRIDE + 4 * j] = make_uint2(*(uint32_t*)&p0, *(uint32_t*)&p1);
        }
        // --- B: 64 q x 64 k bf16 from g_qb ---
        #pragma unroll
        for (int i = 0; i < 2; i++) {
            int id  = tid + 256 * i;        // 0..511
            int row = id >> 3;              // query
            int j   = id & 7;               // uint4 index (8 bf16 each)
            *(uint4*)&sb[row * SA_STRIDE + 8 * j] =
                *(const uint4*)&g_qb[row * DIM + k0c + 8 * j];
        }
        __syncthreads();

        // --- MMA: 4 K-steps of m16n8k16 over 8 n-tiles ---
        const int arow = 16 * wid + g;
        #pragma unroll
        for (int ks = 0; ks < 4; ks++) {
            const int kk = ks * 16 + 2 * tg;
            uint32_t a0 = *(uint32_t*)&sa[arow * SA_STRIDE + kk];
            uint32_t a1 = *(uint32_t*)&sa[(arow + 8) * SA_STRIDE + kk];
            uint32_t a2 = *(uint32_t*)&sa[arow * SA_STRIDE + kk + 8];
            uint32_t a3 = *(uint32_t*)&sa[(arow + 8) * SA_STRIDE + kk + 8];
            #pragma unroll
            for (int nt = 0; nt < 8; nt++) {
                uint32_t b0 = *(uint32_t*)&sb[(nt * 8 + g) * SA_STRIDE + kk];
                uint32_t b1 = *(uint32_t*)&sb[(nt * 8 + g) * SA_STRIDE + kk + 8];
                mma16816(acc[nt][0], acc[nt][1], acc[nt][2], acc[nt][3],
                         a0, a1, a2, a3, b0, b1);
            }
        }
        __syncthreads();   // all LDS reads done before next chunk's STS
    }

    // --- norms: register partials -> shared ---
    #pragma unroll
    for (int i = 0; i < 8; i++)
        atomicAdd(&snrm[(tid >> 4) + 16 * i], npart[i]);
    __syncthreads();

    // --- transpose scaled scores into SMEM (reuse sa): st[q][row] ---
    __nv_bfloat16* st = sa;
    {
        const int arow = 16 * wid + g;
        float nr0 = snrm[arow], nr1 = snrm[arow + 8];
        float s0 = (nr0 > 0.f) ? rsqrtf(nr0) : 0.f;
        float s1 = (nr1 > 0.f) ? rsqrtf(nr1) : 0.f;
        #pragma unroll
        for (int nt = 0; nt < 8; nt++) {
            int q0 = nt * 8 + 2 * tg;
            st[q0 * ST_STRIDE + arow]           = __float2bfloat16(acc[nt][0] * s0);
            st[(q0 + 1) * ST_STRIDE + arow]     = __float2bfloat16(acc[nt][1] * s0);
            st[q0 * ST_STRIDE + arow + 8]       = __float2bfloat16(acc[nt][2] * s1);
            st[(q0 + 1) * ST_STRIDE + arow + 8] = __float2bfloat16(acc[nt][3] * s1);
        }
    }
    __syncthreads();

    // --- coalesced writeback: thread (q = tid>>2, quarter = tid&3) ---
    {
        const int q  = tid >> 2;
        const int c4 = tid & 3;
        #pragma unroll
        for (int u = 0; u < 4; u++) {
            int col = c4 * 32 + 8 * u;
            long n = n0 + col;
            if (n + 8 <= N_FEAT)   // N_FEAT % 8 == 0, tail-safe
                *(uint4*)&g_scores[(size_t)q * N_FEAT + n] =
                    *(uint4*)&st[q * ST_STRIDE + col];
        }
    }
}

// ---------------------------------------------------------------------------
// k2: per query, top-8 over 500000 bf16 scores. 1 block/query.
// ---------------------------------------------------------------------------
__device__ __forceinline__ void insert8(float v, int idx, float tv[NCAND], int ti[NCAND]) {
    if (better(v, idx, tv[NCAND - 1], ti[NCAND - 1])) {
        tv[NCAND - 1] = v; ti[NCAND - 1] = idx;
        #pragma unroll
        for (int s = NCAND - 1; s > 0; s--) {
            if (better(tv[s], ti[s], tv[s - 1], ti[s - 1])) {
                float fv = tv[s]; tv[s] = tv[s - 1]; tv[s - 1] = fv;
                int   fi = ti[s]; ti[s] = ti[s - 1]; ti[s - 1] = fi;
            }
        }
    }
}

__global__ __launch_bounds__(256)
void select_kernel() {
    const int q   = blockIdx.x;
    const int tid = threadIdx.x;

    float tv[NCAND]; int ti[NCAND];
    #pragma unroll
    for (int s = 0; s < NCAND; s++) { tv[s] = -CUDART_INF_F; ti[s] = 0x7fffffff; }

    const uint4* base = (const uint4*)(g_scores + (size_t)q * N_FEAT);
    for (int i = tid; i < N_FEAT / 8; i += 256) {
        uint4 v = base[i];
        __nv_bfloat162* h = (__nv_bfloat162*)&v;
        int bi = i * 8;
        #pragma unroll
        for (int t = 0; t < 4; t++) {
            float2 f = __bfloat1622float2(h[t]);
            insert8(f.x, bi + 2 * t,     tv, ti);
            insert8(f.y, bi + 2 * t + 1, tv, ti);
        }
    }

    __shared__ float sv[256 * NCAND];
    __shared__ int   si[256 * NCAND];
    #pragma unroll
    for (int s = 0; s < NCAND; s++) { sv[tid * NCAND + s] = tv[s]; si[tid * NCAND + s] = ti[s]; }
    __syncthreads();

    for (int off = 128; off >= 1; off >>= 1) {
        if (tid < off) {
            float ov[NCAND]; int oi[NCAND];
            #pragma unroll
            for (int s = 0; s < NCAND; s++) {
                ov[s] = sv[(tid + off) * NCAND + s];
                oi[s] = si[(tid + off) * NCAND + s];
            }
            float mv[NCAND]; int mi[NCAND];
            int a = 0, b = 0;
            #pragma unroll
            for (int o = 0; o < NCAND; o++) {
                if (better(tv[a], ti[a], ov[b], oi[b])) { mv[o] = tv[a]; mi[o] = ti[a]; a++; }
                else                                    { mv[o] = ov[b]; mi[o] = oi[b]; b++; }
            }
            #pragma unroll
            for (int s = 0; s < NCAND; s++) {
                tv[s] = mv[s]; ti[s] = mi[s];
                sv[tid * NCAND + s] = mv[s];
                si[tid * NCAND + s] = mi[s];
            }
        }
        __syncthreads();
    }
    if (tid == 0) {
        #pragma unroll
        for (int s = 0; s < NCAND; s++) g_cand[q * NCAND + s] = ti[s];
    }
}

// ---------------------------------------------------------------------------
// k3: exact fp32 rescore of 8 candidates per query (1 warp per candidate).
// ---------------------------------------------------------------------------
__global__ __launch_bounds__(256)
void rescore_kernel(const float* __restrict__ qf, const float* __restrict__ ff) {
    const int q   = blockIdx.x;
    const int wid = threadIdx.x >> 5;
    const int lid = threadIdx.x & 31;

    int cand = g_cand[q * NCAND + wid];
    cand = (cand < 0) ? 0 : ((cand >= N_FEAT) ? N_FEAT - 1 : cand);

    const float4* fr = (const float4*)&ff[(size_t)cand * DIM];
    const float4* qr = (const float4*)&qf[q * DIM];
    float dot = 0.f, nrm = 0.f;
    for (int t = lid; t < DIM / 4; t += 32) {
        float4 a = fr[t], b = qr[t];
        dot = fmaf(a.x, b.x, fmaf(a.y, b.y, fmaf(a.z, b.z, fmaf(a.w, b.w, dot))));
        nrm = fmaf(a.x, a.x, fmaf(a.y, a.y, fmaf(a.z, a.z, fmaf(a.w, a.w, nrm))));
    }
    #pragma unroll
    for (int off = 16; off >= 1; off >>= 1) {
        dot += __shfl_xor_sync(0xffffffffu, dot, off);
        nrm += __shfl_xor_sync(0xffffffffu, nrm, off);
    }
    if (lid == 0)
        g_exact[q * NCAND + wid] = dot * rsqrtf(nrm);
}

// ---------------------------------------------------------------------------
// k4: exact top-5 of 8 per query.
// ---------------------------------------------------------------------------
__global__ void final_kernel() {
    const int q = threadIdx.x;
    if (q >= NQ) return;
    float v[NCAND]; int ix[NCAND];
    #pragma unroll
    for (int s = 0; s < NCAND; s++) { v[s] = g_exact[q * NCAND + s]; ix[s] = g_cand[q * NCAND + s]; }
    #pragma unroll
    for (int o = 0; o < TOPK; o++) {
        int arg = 0;
        #pragma unroll
        for (int s = 1; s < NCAND; s++)
            if (better(v[s], ix[s], v[arg], ix[arg])) arg = s;
        g_top[q * TOPK + o] = ix[arg];
        v[arg] = -CUDART_INF_F; ix[arg] = 0x7fffffff;
    }
}

// ---------------------------------------------------------------------------
// k5: gather + int->float (output dtype float32).
// ---------------------------------------------------------------------------
__global__ __launch_bounds__(128)
void gather_kernel(const int* __restrict__ data, float* __restrict__ out) {
    const int r = blockIdx.x;
    int idx = g_top[r];
    idx = (idx < 0) ? 0 : ((idx >= N_FEAT) ? N_FEAT - 1 : idx);
    const int4* src = (const int4*)&data[(size_t)idx * SEGLEN];
    float4* dst = (float4*)&out[(size_t)r * SEGLEN];
    for (int t = threadIdx.x; t < SEGLEN / 4; t += blockDim.x) {
        int4 v = src[t];
        dst[t] = make_float4((float)v.x, (float)v.y, (float)v.z, (float)v.w);
    }
}

// ---------------------------------------------------------------------------
extern "C" void kernel_launch(void* const* d_in, const int* in_sizes, int n_in,
                              void* d_out, int out_size) {
    (void)out_size;
    int i_ff = 0, i_dt = -1, i_qf = -1;
    for (int i = 1; i < n_in; i++)
        if ((unsigned)in_sizes[i] > (unsigned)in_sizes[i_ff]) i_ff = i;
    for (int i = 0; i < n_in; i++) {
        if (i == i_ff) continue;
        if (i_dt < 0 || (unsigned)in_sizes[i] > (unsigned)in_sizes[i_dt]) i_dt = i;
    }
    for (int i = 0; i < n_in; i++) {
        if (i == i_ff || i == i_dt) continue;
        if (i_qf < 0 || (unsigned)in_sizes[i] > (unsigned)in_sizes[i_qf]) i_qf = i;
    }
    const float* qf   = (const float*)d_in[i_qf >= 0 ? i_qf : 0];
    const float* ff   = (const float*)d_in[i_ff];
    const int*   data = (const int*)d_in[i_dt >= 0 ? i_dt : (n_in > 2 ? 2 : 0)];
    float* out = (float*)d_out;

    qconv_kernel<<<(NQ * DIM / 2 + 255) / 256, 256>>>(qf);
    mma_score_kernel<<<NBLK, 256>>>(ff);
    select_kernel<<<NQ, 256>>>();
    rescore_kernel<<<NQ, 256>>>(qf, ff);
    final_kernel<<<1, NQ>>>();
    gather_kernel<<<NQ * TOPK, 128>>>(data, out);
}

// round 9
// speedup vs baseline: 11.0697x; 1.3242x over previous
#include <cuda_runtime.h>
#include <cuda_bf16.h>
#include <math_constants.h>
#include <cstdint>

#define N_FEAT 500000
#define DIM    768
#define NQ     64
#define TOPK   5
#define SEGLEN 512
#define M_TILE 128
#define KCH    64
#define NCHUNK (DIM / KCH)                 // 12
#define NBLK   ((N_FEAT + M_TILE - 1) / M_TILE)   // 3907
#define NSEL   16                          // blocks rescored per query

#define SA_STRIDE 72    // bf16 elems per row (64 + 8 pad)

// ---------------- scratch ----------------
__device__ __align__(16) __nv_bfloat16 g_qb[NQ * DIM];
__device__ float g_bmax[(size_t)NQ * NBLK];   // per (query, block) approx max (1MB)
__device__ int   g_top[NQ * TOPK];

__device__ __forceinline__ bool better(float av, int ai, float bv, int bi) {
    return (av > bv) || (av == bv && ai < bi);
}

__device__ __forceinline__ void mma16816(float& c0, float& c1, float& c2, float& c3,
                                         uint32_t a0, uint32_t a1, uint32_t a2, uint32_t a3,
                                         uint32_t b0, uint32_t b1) {
    asm volatile(
        "mma.sync.aligned.m16n8k16.row.col.f32.bf16.bf16.f32 "
        "{%0,%1,%2,%3}, {%4,%5,%6,%7}, {%8,%9}, {%0,%1,%2,%3};"
        : "+f"(c0), "+f"(c1), "+f"(c2), "+f"(c3)
        : "r"(a0), "r"(a1), "r"(a2), "r"(a3), "r"(b0), "r"(b1));
}

// ---------------------------------------------------------------------------
// k0: queries fp32 -> bf16
// ---------------------------------------------------------------------------
__global__ void qconv_kernel(const float* __restrict__ qf) {
    int i = blockIdx.x * 256 + threadIdx.x;
    if (i < NQ * DIM / 2) {
        float2 f = ((const float2*)qf)[i];
        ((__nv_bfloat162*)g_qb)[i] = __float22bfloat162_rn(f);
    }
}

// ---------------------------------------------------------------------------
// k1: bf16 warp-MMA GEMM (128 feat x 64 q, K=768), register-prefetch
//     pipelined; emits per-(query,block) max of scaled scores only
//     (no 64MB score materialization).
// ---------------------------------------------------------------------------
__global__ __launch_bounds__(256)
void mma_score_kernel(const float* __restrict__ ff) {
    __shared__ __nv_bfloat16 sa[M_TILE * SA_STRIDE];   // 18KB
    __shared__ __nv_bfloat16 sb[NQ * SA_STRIDE];       // 9KB
    __shared__ float snrm[M_TILE];
    __shared__ float swmax[8 * NQ];

    const int tid = threadIdx.x;
    const int wid = tid >> 5;
    const int lid = tid & 31;
    const int g   = lid >> 2;
    const int tg  = lid & 3;
    const long n0 = (long)blockIdx.x * M_TILE;

    float acc[8][4];
    #pragma unroll
    for (int nt = 0; nt < 8; nt++)
        #pragma unroll
        for (int r = 0; r < 4; r++) acc[nt][r] = 0.f;
    float npart[8] = {0.f, 0.f, 0.f, 0.f, 0.f, 0.f, 0.f, 0.f};

    float4 ra[8];
    uint4  rb[2];

    // prefetch chunk 0
    #pragma unroll
    for (int i = 0; i < 8; i++) {
        int id  = tid + 256 * i;
        int row = id >> 4;
        int j   = id & 15;
        long n  = n0 + row;
        ra[i] = (n < N_FEAT) ? *(const float4*)&ff[n * (long)DIM + 4 * j]
                             : make_float4(0.f, 0.f, 0.f, 0.f);
    }
    #pragma unroll
    for (int i = 0; i < 2; i++) {
        int id  = tid + 256 * i;
        int row = id >> 3;
        int j   = id & 7;
        rb[i] = *(const uint4*)&g_qb[row * DIM + 8 * j];
    }

    for (int c = 0; c < NCHUNK; c++) {
        // --- convert + STS from prefetched regs (post previous MMA sync) ---
        #pragma unroll
        for (int i = 0; i < 8; i++) {
            int id  = tid + 256 * i;
            int row = id >> 4;
            int j   = id & 15;
            float4 v = ra[i];
            npart[i] = fmaf(v.x, v.x, fmaf(v.y, v.y, fmaf(v.z, v.z, fmaf(v.w, v.w, npart[i]))));
            __nv_bfloat162 p0 = __float22bfloat162_rn(make_float2(v.x, v.y));
            __nv_bfloat162 p1 = __float22bfloat162_rn(make_float2(v.z, v.w));
            *(uint2*)&sa[row * SA_STRIDE + 4 * j] = make_uint2(*(uint32_t*)&p0, *(uint32_t*)&p1);
        }
        #pragma unroll
        for (int i = 0; i < 2; i++) {
            int id  = tid + 256 * i;
            int row = id >> 3;
            int j   = id & 7;
            *(uint4*)&sb[row * SA_STRIDE + 8 * j] = rb[i];
        }
        // --- issue next chunk's LDGs (in flight through sync + MMA) ---
        if (c + 1 < NCHUNK) {
            const int k0n = (c + 1) * KCH;
            #pragma unroll
            for (int i = 0; i < 8; i++) {
                int id  = tid + 256 * i;
                int row = id >> 4;
                int j   = id & 15;
                long n  = n0 + row;
                ra[i] = (n < N_FEAT) ? *(const float4*)&ff[n * (long)DIM + k0n + 4 * j]
                                     : make_float4(0.f, 0.f, 0.f, 0.f);
            }
            #pragma unroll
            for (int i = 0; i < 2; i++) {
                int id  = tid + 256 * i;
                int row = id >> 3;
                int j   = id & 7;
                rb[i] = *(const uint4*)&g_qb[row * DIM + k0n + 8 * j];
            }
        }
        __syncthreads();

        // --- MMA: 4 K-steps of m16n8k16 over 8 n-tiles ---
        const int arow = 16 * wid + g;
        #pragma unroll
        for (int ks = 0; ks < 4; ks++) {
            const int kk = ks * 16 + 2 * tg;
            uint32_t a0 = *(uint32_t*)&sa[arow * SA_STRIDE + kk];
            uint32_t a1 = *(uint32_t*)&sa[(arow + 8) * SA_STRIDE + kk];
            uint32_t a2 = *(uint32_t*)&sa[arow * SA_STRIDE + kk + 8];
            uint32_t a3 = *(uint32_t*)&sa[(arow + 8) * SA_STRIDE + kk + 8];
            #pragma unroll
            for (int nt = 0; nt < 8; nt++) {
                uint32_t b0 = *(uint32_t*)&sb[(nt * 8 + g) * SA_STRIDE + kk];
                uint32_t b1 = *(uint32_t*)&sb[(nt * 8 + g) * SA_STRIDE + kk + 8];
                mma16816(acc[nt][0], acc[nt][1], acc[nt][2], acc[nt][3],
                         a0, a1, a2, a3, b0, b1);
            }
        }
        __syncthreads();
    }

    // --- norms: shuffle-reduce over the 16 lanes sharing each row ---
    #pragma unroll
    for (int i = 0; i < 8; i++) {
        float v = npart[i];
        v += __shfl_xor_sync(0xffffffffu, v, 1);
        v += __shfl_xor_sync(0xffffffffu, v, 2);
        v += __shfl_xor_sync(0xffffffffu, v, 4);
        v += __shfl_xor_sync(0xffffffffu, v, 8);
        if ((tid & 15) == 0) snrm[(tid >> 4) + 16 * i] = v;
    }
    __syncthreads();

    // --- per-(query,block) max of scaled scores ---
    {
        const int arow = 16 * wid + g;
        float nr0 = snrm[arow], nr1 = snrm[arow + 8];
        float s0 = (nr0 > 0.f) ? rsqrtf(nr0) : 0.f;
        float s1 = (nr1 > 0.f) ? rsqrtf(nr1) : 0.f;
        bool ok0 = (n0 + arow)     < N_FEAT;
        bool ok1 = (n0 + arow + 8) < N_FEAT;
        #pragma unroll
        for (int nt = 0; nt < 8; nt++) {
            float v0 = fmaxf(ok0 ? acc[nt][0] * s0 : -CUDART_INF_F,
                             ok1 ? acc[nt][2] * s1 : -CUDART_INF_F);
            float v1 = fmaxf(ok0 ? acc[nt][1] * s0 : -CUDART_INF_F,
                             ok1 ? acc[nt][3] * s1 : -CUDART_INF_F);
            #pragma unroll
            for (int off = 4; off <= 16; off <<= 1) {   // reduce over g (lane stride 4)
                v0 = fmaxf(v0, __shfl_xor_sync(0xffffffffu, v0, off));
                v1 = fmaxf(v1, __shfl_xor_sync(0xffffffffu, v1, off));
            }
            if (g == 0) {
                swmax[wid * NQ + nt * 8 + 2 * tg]     = v0;
                swmax[wid * NQ + nt * 8 + 2 * tg + 1] = v1;
            }
        }
    }
    __syncthreads();
    if (tid < NQ) {
        float m = swmax[tid];
        #pragma unroll
        for (int w = 1; w < 8; w++) m = fmaxf(m, swmax[w * NQ + tid]);
        g_bmax[(size_t)tid * NBLK + blockIdx.x] = m;
    }
}

// ---------------------------------------------------------------------------
// k2 (fused): per query — top-16 blocks by approx max, exact fp32 rescore of
// their 2048 rows, final top-5. One block per query, 256 threads.
// ---------------------------------------------------------------------------
__device__ __forceinline__ void insert5(float v, int idx, float tv[5], int ti[5]) {
    if (better(v, idx, tv[4], ti[4])) {
        tv[4] = v; ti[4] = idx;
        #pragma unroll
        for (int s = 4; s > 0; s--) {
            if (better(tv[s], ti[s], tv[s - 1], ti[s - 1])) {
                float fv = tv[s]; tv[s] = tv[s - 1]; tv[s - 1] = fv;
                int   fi = ti[s]; ti[s] = ti[s - 1]; ti[s - 1] = fi;
            }
        }
    }
}

__global__ __launch_bounds__(256)
void select_rescore_kernel(const float* __restrict__ qf, const float* __restrict__ ff) {
    __shared__ float sval[NBLK];
    __shared__ int   sblk[NSEL];
    __shared__ float swv[8];  __shared__ int swi[8];
    __shared__ float wtv[8][TOPK]; __shared__ int wti[8][TOPK];

    const int q   = blockIdx.x;
    const int tid = threadIdx.x;
    const int wid = tid >> 5;
    const int lid = tid & 31;

    for (int b = tid; b < NBLK; b += 256)
        sval[b] = g_bmax[(size_t)q * NBLK + b];
    __syncthreads();

    // Phase A: 16 argmax rounds
    for (int r = 0; r < NSEL; r++) {
        float bv = -CUDART_INF_F; int bi = 0x7fffffff;
        for (int b = tid; b < NBLK; b += 256)
            if (better(sval[b], b, bv, bi)) { bv = sval[b]; bi = b; }
        #pragma unroll
        for (int off = 16; off >= 1; off >>= 1) {
            float ov = __shfl_xor_sync(0xffffffffu, bv, off);
            int   oi = __shfl_xor_sync(0xffffffffu, bi, off);
            if (better(ov, oi, bv, bi)) { bv = ov; bi = oi; }
        }
        if (lid == 0) { swv[wid] = bv; swi[wid] = bi; }
        __syncthreads();
        if (tid == 0) {
            float mv = swv[0]; int mi = swi[0];
            #pragma unroll
            for (int w = 1; w < 8; w++)
                if (better(swv[w], swi[w], mv, mi)) { mv = swv[w]; mi = swi[w]; }
            sblk[r] = mi;
            sval[mi] = -CUDART_INF_F;
        }
        __syncthreads();
    }

    // Phase B: exact fp32 rescore, one warp per row.
    float tv[TOPK]; int ti[TOPK];
    #pragma unroll
    for (int s = 0; s < TOPK; s++) { tv[s] = -CUDART_INF_F; ti[s] = 0x7fffffff; }

    const float4* qr = (const float4*)&qf[q * DIM];
    for (int e = wid; e < NSEL * M_TILE; e += 8) {
        long row = (long)sblk[e >> 7] * M_TILE + (e & 127);
        if (row < N_FEAT) {
            const float4* fr = (const float4*)&ff[row * (long)DIM];
            float dot = 0.f, nr = 0.f;
            #pragma unroll
            for (int u = 0; u < 6; u++) {
                float4 a = fr[lid + 32 * u];
                float4 b = qr[lid + 32 * u];
                dot = fmaf(a.x, b.x, fmaf(a.y, b.y, fmaf(a.z, b.z, fmaf(a.w, b.w, dot))));
                nr  = fmaf(a.x, a.x, fmaf(a.y, a.y, fmaf(a.z, a.z, fmaf(a.w, a.w, nr))));
            }
            #pragma unroll
            for (int off = 16; off >= 1; off >>= 1) {
                dot += __shfl_xor_sync(0xffffffffu, dot, off);
                nr  += __shfl_xor_sync(0xffffffffu, nr,  off);
            }
            if (lid == 0)
                insert5(dot * rsqrtf(nr), (int)row, tv, ti);
        }
    }
    if (lid == 0) {
        #pragma unroll
        for (int s = 0; s < TOPK; s++) { wtv[wid][s] = tv[s]; wti[wid][s] = ti[s]; }
    }
    __syncthreads();

    if (tid == 0) {
        float cv[8 * TOPK]; int ci[8 * TOPK];
        for (int e = 0; e < 8 * TOPK; e++) { cv[e] = wtv[e / TOPK][e % TOPK]; ci[e] = wti[e / TOPK][e % TOPK]; }
        for (int o = 0; o < TOPK; o++) {
            int arg = 0;
            for (int e = 1; e < 8 * TOPK; e++)
                if (better(cv[e], ci[e], cv[arg], ci[arg])) arg = e;
            g_top[q * TOPK + o] = ci[arg];
            cv[arg] = -CUDART_INF_F; ci[arg] = 0x7fffffff;
        }
    }
}

// ---------------------------------------------------------------------------
// k3: gather + int->float (output dtype float32).
// ---------------------------------------------------------------------------
__global__ __launch_bounds__(128)
void gather_kernel(const int* __restrict__ data, float* __restrict__ out) {
    const int r = blockIdx.x;
    int idx = g_top[r];
    idx = (idx < 0) ? 0 : ((idx >= N_FEAT) ? N_FEAT - 1 : idx);
    const int4* src = (const int4*)&data[(size_t)idx * SEGLEN];
    float4* dst = (float4*)&out[(size_t)r * SEGLEN];
    for (int t = threadIdx.x; t < SEGLEN / 4; t += blockDim.x) {
        int4 v = src[t];
        dst[t] = make_float4((float)v.x, (float)v.y, (float)v.z, (float)v.w);
    }
}

// ---------------------------------------------------------------------------
extern "C" void kernel_launch(void* const* d_in, const int* in_sizes, int n_in,
                              void* d_out, int out_size) {
    (void)out_size;
    int i_ff = 0, i_dt = -1, i_qf = -1;
    for (int i = 1; i < n_in; i++)
        if ((unsigned)in_sizes[i] > (unsigned)in_sizes[i_ff]) i_ff = i;
    for (int i = 0; i < n_in; i++) {
        if (i == i_ff) continue;
        if (i_dt < 0 || (unsigned)in_sizes[i] > (unsigned)in_sizes[i_dt]) i_dt = i;
    }
    for (int i = 0; i < n_in; i++) {
        if (i == i_ff || i == i_dt) continue;
        if (i_qf < 0 || (unsigned)in_sizes[i] > (unsigned)in_sizes[i_qf]) i_qf = i;
    }
    const float* qf   = (const float*)d_in[i_qf >= 0 ? i_qf : 0];
    const float* ff   = (const float*)d_in[i_ff];
    const int*   data = (const int*)d_in[i_dt >= 0 ? i_dt : (n_in > 2 ? 2 : 0)];
    float* out = (float*)d_out;

    qconv_kernel<<<(NQ * DIM / 2 + 255) / 256, 256>>>(qf);
    mma_score_kernel<<<NBLK, 256>>>(ff);
    select_rescore_kernel<<<NQ, 256>>>(qf, ff);
    gather_kernel<<<NQ * TOPK, 128>>>(data, out);
}

// round 10
// speedup vs baseline: 11.0784x; 1.0008x over previous
#include <cuda_runtime.h>
#include <cuda_bf16.h>
#include <math_constants.h>
#include <cstdint>

#define N_FEAT 500000
#define DIM    768
#define NQ     64
#define TOPK   5
#define SEGLEN 512
#define M_TILE 128
#define KCH    64
#define NCHUNK (DIM / KCH)                 // 12
#define NBLK   ((N_FEAT + M_TILE - 1) / M_TILE)   // 3907
#define NSEL   16

#define SA_STRIDE 72    // bf16 elems per row (64 + 8 pad): 144B rows -> ldmatrix conflict-free

// ---------------- scratch ----------------
__device__ __align__(16) __nv_bfloat16 g_qb[NQ * DIM];
__device__ float g_bmax[(size_t)NQ * NBLK];
__device__ int   g_top[NQ * TOPK];

__device__ __forceinline__ bool better(float av, int ai, float bv, int bi) {
    return (av > bv) || (av == bv && ai < bi);
}

__device__ __forceinline__ uint32_t smem_u32(const void* p) {
    return (uint32_t)__cvta_generic_to_shared(p);
}

__device__ __forceinline__ void mma16816(float& c0, float& c1, float& c2, float& c3,
                                         uint32_t a0, uint32_t a1, uint32_t a2, uint32_t a3,
                                         uint32_t b0, uint32_t b1) {
    asm volatile(
        "mma.sync.aligned.m16n8k16.row.col.f32.bf16.bf16.f32 "
        "{%0,%1,%2,%3}, {%4,%5,%6,%7}, {%8,%9}, {%0,%1,%2,%3};"
        : "+f"(c0), "+f"(c1), "+f"(c2), "+f"(c3)
        : "r"(a0), "r"(a1), "r"(a2), "r"(a3), "r"(b0), "r"(b1));
}

__device__ __forceinline__ void ldmatrix_x4(uint32_t& r0, uint32_t& r1, uint32_t& r2,
                                            uint32_t& r3, uint32_t addr) {
    asm volatile("ldmatrix.sync.aligned.m8n8.x4.shared.b16 {%0,%1,%2,%3}, [%4];"
                 : "=r"(r0), "=r"(r1), "=r"(r2), "=r"(r3) : "r"(addr));
}

// ---------------------------------------------------------------------------
// k0: queries fp32 -> bf16
// ---------------------------------------------------------------------------
__global__ void qconv_kernel(const float* __restrict__ qf) {
    int i = blockIdx.x * 256 + threadIdx.x;
    if (i < NQ * DIM / 2) {
        float2 f = ((const float2*)qf)[i];
        ((__nv_bfloat162*)g_qb)[i] = __float22bfloat162_rn(f);
    }
}

// ---------------------------------------------------------------------------
// k1: bf16 warp-MMA GEMM, double-buffered SMEM (1 sync/chunk), ldmatrix
//     fragment loads (20 vs 80 LDS per warp-chunk), 2-deep LDG pipeline.
//     Emits per-(query,block) max of scaled scores.
// ---------------------------------------------------------------------------
__global__ __launch_bounds__(256)
void mma_score_kernel(const float* __restrict__ ff) {
    __shared__ __nv_bfloat16 sa[2][M_TILE * SA_STRIDE];   // 2 x 18KB
    __shared__ __nv_bfloat16 sb[2][NQ * SA_STRIDE];       // 2 x 9KB
    __shared__ float snrm[M_TILE];
    __shared__ float swmax[8 * NQ];

    const int tid = threadIdx.x;
    const int wid = tid >> 5;
    const int lid = tid & 31;
    const int g   = lid >> 2;
    const int tg  = lid & 3;
    const long n0 = (long)blockIdx.x * M_TILE;

    // per-lane ldmatrix byte offsets (relative to buffer base, ks = 0)
    const int mm = lid >> 3;                         // matrix index 0..3
    const uint32_t a_off =
        (uint32_t)(((16 * wid + (lid & 7) + (mm & 1) * 8) * SA_STRIDE + (mm >> 1) * 8) * 2);
    const uint32_t b_off =
        (uint32_t)((((lid & 7) + (mm >> 1) * 8) * SA_STRIDE + (mm & 1) * 8) * 2);
    const uint32_t sa_base0 = smem_u32(&sa[0][0]);
    const uint32_t sa_base1 = smem_u32(&sa[1][0]);
    const uint32_t sb_base0 = smem_u32(&sb[0][0]);
    const uint32_t sb_base1 = smem_u32(&sb[1][0]);

    float acc[8][4];
    #pragma unroll
    for (int nt = 0; nt < 8; nt++)
        #pragma unroll
        for (int r = 0; r < 4; r++) acc[nt][r] = 0.f;
    float npart[8] = {0.f, 0.f, 0.f, 0.f, 0.f, 0.f, 0.f, 0.f};

    float4 ra[8];
    uint4  rb[2];

    // ---- helpers as lambdas ----
    auto ldg_chunk = [&](int c) {
        const int k0c = c * KCH;
        #pragma unroll
        for (int i = 0; i < 8; i++) {
            int id  = tid + 256 * i;
            int row = id >> 4;
            int j   = id & 15;
            long n  = n0 + row;
            ra[i] = (n < N_FEAT) ? *(const float4*)&ff[n * (long)DIM + k0c + 4 * j]
                                 : make_float4(0.f, 0.f, 0.f, 0.f);
        }
        #pragma unroll
        for (int i = 0; i < 2; i++) {
            int id  = tid + 256 * i;
            int row = id >> 3;
            int j   = id & 7;
            rb[i] = *(const uint4*)&g_qb[row * DIM + k0c + 8 * j];
        }
    };
    auto sts_chunk = [&](int buf) {
        #pragma unroll
        for (int i = 0; i < 8; i++) {
            int id  = tid + 256 * i;
            int row = id >> 4;
            int j   = id & 15;
            float4 v = ra[i];
            npart[i] = fmaf(v.x, v.x, fmaf(v.y, v.y, fmaf(v.z, v.z, fmaf(v.w, v.w, npart[i]))));
            __nv_bfloat162 p0 = __float22bfloat162_rn(make_float2(v.x, v.y));
            __nv_bfloat162 p1 = __float22bfloat162_rn(make_float2(v.z, v.w));
            *(uint2*)&sa[buf][row * SA_STRIDE + 4 * j] =
                make_uint2(*(uint32_t*)&p0, *(uint32_t*)&p1);
        }
        #pragma unroll
        for (int i = 0; i < 2; i++) {
            int id  = tid + 256 * i;
            int row = id >> 3;
            int j   = id & 7;
            *(uint4*)&sb[buf][row * SA_STRIDE + 8 * j] = rb[i];
        }
    };

    // ---- prologue ----
    ldg_chunk(0);
    sts_chunk(0);
    if (NCHUNK > 1) ldg_chunk(1);
    __syncthreads();

    // ---- main loop: one sync per chunk ----
    for (int c = 0; c < NCHUNK; c++) {
        if (c + 1 < NCHUNK) {
            sts_chunk((c + 1) & 1);
            if (c + 2 < NCHUNK) ldg_chunk(c + 2);
        }
        const uint32_t sabuf = (c & 1) ? sa_base1 : sa_base0;
        const uint32_t sbbuf = (c & 1) ? sb_base1 : sb_base0;

        #pragma unroll
        for (int ks = 0; ks < 4; ks++) {
            uint32_t a0, a1, a2, a3;
            ldmatrix_x4(a0, a1, a2, a3, sabuf + a_off + ks * 32);
            #pragma unroll
            for (int ntp = 0; ntp < 4; ntp++) {
                uint32_t b00, b01, b10, b11;
                ldmatrix_x4(b00, b01, b10, b11,
                            sbbuf + b_off + (uint32_t)(ntp * 16 * SA_STRIDE * 2) + ks * 32);
                mma16816(acc[2 * ntp][0], acc[2 * ntp][1], acc[2 * ntp][2], acc[2 * ntp][3],
                         a0, a1, a2, a3, b00, b01);
                mma16816(acc[2 * ntp + 1][0], acc[2 * ntp + 1][1],
                         acc[2 * ntp + 1][2], acc[2 * ntp + 1][3],
                         a0, a1, a2, a3, b10, b11);
            }
        }
        __syncthreads();
    }

    // ---- norms: shuffle-reduce over the 16 lanes sharing each row ----
    #pragma unroll
    for (int i = 0; i < 8; i++) {
        float v = npart[i];
        v += __shfl_xor_sync(0xffffffffu, v, 1);
        v += __shfl_xor_sync(0xffffffffu, v, 2);
        v += __shfl_xor_sync(0xffffffffu, v, 4);
        v += __shfl_xor_sync(0xffffffffu, v, 8);
        if ((tid & 15) == 0) snrm[(tid >> 4) + 16 * i] = v;
    }
    __syncthreads();

    // ---- per-(query,block) max of scaled scores ----
    {
        const int arow = 16 * wid + g;
        float nr0 = snrm[arow], nr1 = snrm[arow + 8];
        float s0 = (nr0 > 0.f) ? rsqrtf(nr0) : 0.f;
        float s1 = (nr1 > 0.f) ? rsqrtf(nr1) : 0.f;
        bool ok0 = (n0 + arow)     < N_FEAT;
        bool ok1 = (n0 + arow + 8) < N_FEAT;
        #pragma unroll
        for (int nt = 0; nt < 8; nt++) {
            float v0 = fmaxf(ok0 ? acc[nt][0] * s0 : -CUDART_INF_F,
                             ok1 ? acc[nt][2] * s1 : -CUDART_INF_F);
            float v1 = fmaxf(ok0 ? acc[nt][1] * s0 : -CUDART_INF_F,
                             ok1 ? acc[nt][3] * s1 : -CUDART_INF_F);
            #pragma unroll
            for (int off = 4; off <= 16; off <<= 1) {
                v0 = fmaxf(v0, __shfl_xor_sync(0xffffffffu, v0, off));
                v1 = fmaxf(v1, __shfl_xor_sync(0xffffffffu, v1, off));
            }
            if (g == 0) {
                swmax[wid * NQ + nt * 8 + 2 * tg]     = v0;
                swmax[wid * NQ + nt * 8 + 2 * tg + 1] = v1;
            }
        }
    }
    __syncthreads();
    if (tid < NQ) {
        float m = swmax[tid];
        #pragma unroll
        for (int w = 1; w < 8; w++) m = fmaxf(m, swmax[w * NQ + tid]);
        g_bmax[(size_t)tid * NBLK + blockIdx.x] = m;
    }
}

// ---------------------------------------------------------------------------
// k2 (fused): per query — top-16 blocks by approx max, exact fp32 rescore,
// final top-5.
// ---------------------------------------------------------------------------
__device__ __forceinline__ void insert5(float v, int idx, float tv[5], int ti[5]) {
    if (better(v, idx, tv[4], ti[4])) {
        tv[4] = v; ti[4] = idx;
        #pragma unroll
        for (int s = 4; s > 0; s--) {
            if (better(tv[s], ti[s], tv[s - 1], ti[s - 1])) {
                float fv = tv[s]; tv[s] = tv[s - 1]; tv[s - 1] = fv;
                int   fi = ti[s]; ti[s] = ti[s - 1]; ti[s - 1] = fi;
            }
        }
    }
}

__global__ __launch_bounds__(256)
void select_rescore_kernel(const float* __restrict__ qf, const float* __restrict__ ff) {
    __shared__ float sval[NBLK];
    __shared__ int   sblk[NSEL];
    __shared__ float swv[8];  __shared__ int swi[8];
    __shared__ float wtv[8][TOPK]; __shared__ int wti[8][TOPK];

    const int q   = blockIdx.x;
    const int tid = threadIdx.x;
    const int wid = tid >> 5;
    const int lid = tid & 31;

    for (int b = tid; b < NBLK; b += 256)
        sval[b] = g_bmax[(size_t)q * NBLK + b];
    __syncthreads();

    for (int r = 0; r < NSEL; r++) {
        float bv = -CUDART_INF_F; int bi = 0x7fffffff;
        for (int b = tid; b < NBLK; b += 256)
            if (better(sval[b], b, bv, bi)) { bv = sval[b]; bi = b; }
        #pragma unroll
        for (int off = 16; off >= 1; off >>= 1) {
            float ov = __shfl_xor_sync(0xffffffffu, bv, off);
            int   oi = __shfl_xor_sync(0xffffffffu, bi, off);
            if (better(ov, oi, bv, bi)) { bv = ov; bi = oi; }
        }
        if (lid == 0) { swv[wid] = bv; swi[wid] = bi; }
        __syncthreads();
        if (tid == 0) {
            float mv = swv[0]; int mi = swi[0];
            #pragma unroll
            for (int w = 1; w < 8; w++)
                if (better(swv[w], swi[w], mv, mi)) { mv = swv[w]; mi = swi[w]; }
            sblk[r] = mi;
            sval[mi] = -CUDART_INF_F;
        }
        __syncthreads();
    }

    float tv[TOPK]; int ti[TOPK];
    #pragma unroll
    for (int s = 0; s < TOPK; s++) { tv[s] = -CUDART_INF_F; ti[s] = 0x7fffffff; }

    const float4* qr = (const float4*)&qf[q * DIM];
    for (int e = wid; e < NSEL * M_TILE; e += 8) {
        long row = (long)sblk[e >> 7] * M_TILE + (e & 127);
        if (row < N_FEAT) {
            const float4* fr = (const float4*)&ff[row * (long)DIM];
            float dot = 0.f, nr = 0.f;
            #pragma unroll
            for (int u = 0; u < 6; u++) {
                float4 a = fr[lid + 32 * u];
                float4 b = qr[lid + 32 * u];
                dot = fmaf(a.x, b.x, fmaf(a.y, b.y, fmaf(a.z, b.z, fmaf(a.w, b.w, dot))));
                nr  = fmaf(a.x, a.x, fmaf(a.y, a.y, fmaf(a.z, a.z, fmaf(a.w, a.w, nr))));
            }
            #pragma unroll
            for (int off = 16; off >= 1; off >>= 1) {
                dot += __shfl_xor_sync(0xffffffffu, dot, off);
                nr  += __shfl_xor_sync(0xffffffffu, nr,  off);
            }
            if (lid == 0)
                insert5(dot * rsqrtf(nr), (int)row, tv, ti);
        }
    }
    if (lid == 0) {
        #pragma unroll
        for (int s = 0; s < TOPK; s++) { wtv[wid][s] = tv[s]; wti[wid][s] = ti[s]; }
    }
    __syncthreads();

    if (tid == 0) {
        float cv[8 * TOPK]; int ci[8 * TOPK];
        for (int e = 0; e < 8 * TOPK; e++) { cv[e] = wtv[e / TOPK][e % TOPK]; ci[e] = wti[e / TOPK][e % TOPK]; }
        for (int o = 0; o < TOPK; o++) {
            int arg = 0;
            for (int e = 1; e < 8 * TOPK; e++)
                if (better(cv[e], ci[e], cv[arg], ci[arg])) arg = e;
            g_top[q * TOPK + o] = ci[arg];
            cv[arg] = -CUDART_INF_F; ci[arg] = 0x7fffffff;
        }
    }
}

// ---------------------------------------------------------------------------
// k3: gather + int->float (output dtype float32).
// ---------------------------------------------------------------------------
__global__ __launch_bounds__(128)
void gather_kernel(const int* __restrict__ data, float* __restrict__ out) {
    const int r = blockIdx.x;
    int idx = g_top[r];
    idx = (idx < 0) ? 0 : ((idx >= N_FEAT) ? N_FEAT - 1 : idx);
    const int4* src = (const int4*)&data[(size_t)idx * SEGLEN];
    float4* dst = (float4*)&out[(size_t)r * SEGLEN];
    for (int t = threadIdx.x; t < SEGLEN / 4; t += blockDim.x) {
        int4 v = src[t];
        dst[t] = make_float4((float)v.x, (float)v.y, (float)v.z, (float)v.w);
    }
}

// ---------------------------------------------------------------------------
extern "C" void kernel_launch(void* const* d_in, const int* in_sizes, int n_in,
                              void* d_out, int out_size) {
    (void)out_size;
    int i_ff = 0, i_dt = -1, i_qf = -1;
    for (int i = 1; i < n_in; i++)
        if ((unsigned)in_sizes[i] > (unsigned)in_sizes[i_ff]) i_ff = i;
    for (int i = 0; i < n_in; i++) {
        if (i == i_ff) continue;
        if (i_dt < 0 || (unsigned)in_sizes[i] > (unsigned)in_sizes[i_dt]) i_dt = i;
    }
    for (int i = 0; i < n_in; i++) {
        if (i == i_ff || i == i_dt) continue;
        if (i_qf < 0 || (unsigned)in_sizes[i] > (unsigned)in_sizes[i_qf]) i_qf = i;
    }
    const float* qf   = (const float*)d_in[i_qf >= 0 ? i_qf : 0];
    const float* ff   = (const float*)d_in[i_ff];
    const int*   data = (const int*)d_in[i_dt >= 0 ? i_dt : (n_in > 2 ? 2 : 0)];
    float* out = (float*)d_out;

    qconv_kernel<<<(NQ * DIM / 2 + 255) / 256, 256>>>(qf);
    mma_score_kernel<<<NBLK, 256>>>(ff);
    select_rescore_kernel<<<NQ, 256>>>(qf, ff);
    gather_kernel<<<NQ * TOPK, 128>>>(data, out);
}